// round 11
// baseline (speedup 1.0000x reference)
#include <cuda_runtime.h>
#include <cstdint>

#define FULLMASK 0xffffffffu

static __device__ __forceinline__ float fixv(float p) {
    return (p == -1.0f) ? 0.0f : p;
}

static __device__ __forceinline__ float tanh_fast(float x) {
    float y;
    asm("tanh.approx.f32 %0, %1;" : "=f"(y) : "f"(x));
    return y;
}

// ---- packed f32x2 helpers (Blackwell: add.rn.f32x2 / fma.rn.f32x2) ----
static __device__ __forceinline__ uint64_t pk(float lo, float hi) {
    uint64_t r;
    asm("mov.b64 %0, {%1, %2};" : "=l"(r) : "f"(lo), "f"(hi));
    return r;
}
static __device__ __forceinline__ void upk(uint64_t v, float& lo, float& hi) {
    asm("mov.b64 {%0, %1}, %2;" : "=f"(lo), "=f"(hi) : "l"(v));
}
static __device__ __forceinline__ uint64_t addx2(uint64_t a, uint64_t b) {
    uint64_t r;
    asm("add.rn.f32x2 %0, %1, %2;" : "=l"(r) : "l"(a), "l"(b));
    return r;
}
static __device__ __forceinline__ uint64_t fmax2(uint64_t a, uint64_t b, uint64_t c) {
    uint64_t r;
    asm("fma.rn.f32x2 %0, %1, %2, %3;" : "=l"(r) : "l"(a), "l"(b), "l"(c));
    return r;
}

// One CTA per batch image, 512 threads, 2 cols x 4 rows per thread.
// Warp w (of 16) owns image rows 4w..4w+3; lane j owns cols 2j,2j+1.
//
// R10 structure (register-resident interior, boundary-only smem, interior
// tanh hidden behind the barrier) with all float2 arithmetic packed into
// f32x2 instructions (FFMA2 / packed FADD) to cut the issue count.
__global__ __launch_bounds__(512, 1)
void prop_kernel(const float* __restrict__ X,
                 const float* __restrict__ pred,
                 const float* __restrict__ w,
                 const float* __restrict__ a,
                 const float* __restrict__ bias,
                 const float* __restrict__ scalar,
                 float* __restrict__ out)
{
    constexpr int NS = 64;          // image side
    constexpr int HH = NS * NS;     // 4096 pixels
    constexpr int SROWS = 66;       // +1 zero halo row each side (idx = row+1)
    constexpr int ITERS = 12;

    __shared__ float Hs[2][SROWS * NS];   // boundary h-rows, double buffered

    const int b    = blockIdx.x;
    const int t    = threadIdx.x;
    const int wrp  = t >> 5;        // 0..15 -> rows 4w..4w+3
    const int lane = t & 31;        // cols 2j, 2j+1

    // Zero halo rows (halo idx 0 and 65) in both buffers, once.
    if (t < NS) {
        Hs[0][t] = 0.f;            Hs[1][t] = 0.f;
        Hs[0][65 * NS + t] = 0.f;  Hs[1][65 * NS + t] = 0.f;
    }

    const float s  = scalar[0];
    const int r0 = wrp * 4;             // first owned row
    const int c  = lane * 2;            // left col
    const int g0 = b * HH + r0 * NS + c;
    const int p0 = r0 * NS + c;

    // ---- per-row params: CS = s*(u_fix+bias+a*X), SW = s*w (packed) ----
    float2 u0, u1, u2, u3;              // state, one float2 per row
    uint64_t CS0, CS1, CS2, CS3, SW0, SW1, SW2, SW3;
    {
        float2 pr, xx, ww, aa, bb;
        #define SETUP(K)                                                     \
            pr = *(const float2*)(pred + g0 + (K) * NS);                     \
            xx = *(const float2*)(X    + g0 + (K) * NS);                     \
            ww = *(const float2*)(w    + p0 + (K) * NS);                     \
            aa = *(const float2*)(a    + p0 + (K) * NS);                     \
            bb = *(const float2*)(bias + p0 + (K) * NS);                     \
            CS##K = pk(s * (fixv(pr.x) + bb.x + aa.x * xx.x),                \
                       s * (fixv(pr.y) + bb.y + aa.y * xx.y));               \
            SW##K = pk(s * ww.x, s * ww.y);                                  \
            u##K = pr;
        SETUP(0) SETUP(1) SETUP(2) SETUP(3)
        #undef SETUP
    }

    // smem indices (image row r -> halo idx r+1)
    const int stT = (r0 + 1) * NS + c;   // own top boundary h-row (row 4w)
    const int stB = (r0 + 4) * NS + c;   // own bottom boundary h-row (row 4w+3)
    const int ldU =  r0      * NS + c;   // halo above (row 4w-1)
    const int ldD = (r0 + 5) * NS + c;   // halo below (row 4w+4)

    __syncthreads();

    #pragma unroll
    for (int it = 0; it < ITERS; ++it) {
        float* __restrict__ Hc = Hs[it & 1];

        // ---- horizontal 3-sums for all 4 owned rows (8 shuffles) ----
        float s0 = u0.x + u0.y, s1 = u1.x + u1.y;
        float s2 = u2.x + u2.y, s3 = u3.x + u3.y;
        float l0 = __shfl_up_sync  (FULLMASK, u0.y, 1);
        float r0s= __shfl_down_sync(FULLMASK, u0.x, 1);
        float l1 = __shfl_up_sync  (FULLMASK, u1.y, 1);
        float r1s= __shfl_down_sync(FULLMASK, u1.x, 1);
        float l2 = __shfl_up_sync  (FULLMASK, u2.y, 1);
        float r2s= __shfl_down_sync(FULLMASK, u2.x, 1);
        float l3 = __shfl_up_sync  (FULLMASK, u3.y, 1);
        float r3s= __shfl_down_sync(FULLMASK, u3.x, 1);
        if (lane == 0)  { l0 = 0.f; l1 = 0.f; l2 = 0.f; l3 = 0.f; }
        if (lane == 31) { r0s = 0.f; r1s = 0.f; r2s = 0.f; r3s = 0.f; }

        // packed h-rows: H_k = (l+s, s+r) via packed add
        uint64_t H0 = addx2(pk(l0, s0), pk(s0, r0s));
        uint64_t H1 = addx2(pk(l1, s1), pk(s1, r1s));
        uint64_t H2 = addx2(pk(l2, s2), pk(s2, r2s));
        uint64_t H3 = addx2(pk(l3, s3), pk(s3, r3s));

        // ---- publish boundary rows only (STS.64) ----
        *(uint64_t*)&Hc[stT] = H0;
        *(uint64_t*)&Hc[stB] = H3;

        // ---- interior outputs (no smem dependency): before the barrier ----
        uint64_t P  = addx2(H1, H2);        // h1+h2
        uint64_t V1 = addx2(H0, P);         // h0+h1+h2
        uint64_t V2 = addx2(P, H3);         // h1+h2+h3
        uint64_t U1 = fmax2(SW1, V1, CS1);
        uint64_t U2 = fmax2(SW2, V2, CS2);
        {
            float x1, y1, x2, y2;
            upk(U1, x1, y1);  upk(U2, x2, y2);
            u1.x = tanh_fast(x1);  u1.y = tanh_fast(y1);
            u2.x = tanh_fast(x2);  u2.y = tanh_fast(y2);
        }

        // partial boundary sums
        uint64_t T0 = addx2(H0, H1);
        uint64_t T3 = addx2(H2, H3);

        __syncthreads();

        // ---- halo h-rows, finish boundary outputs ----
        const uint64_t HU = *(const uint64_t*)&Hc[ldU];
        const uint64_t HD = *(const uint64_t*)&Hc[ldD];

        uint64_t U0 = fmax2(SW0, addx2(HU, T0), CS0);
        uint64_t U3 = fmax2(SW3, addx2(T3, HD), CS3);
        {
            float x0, y0, x3, y3;
            upk(U0, x0, y0);  upk(U3, x3, y3);
            u0.x = tanh_fast(x0);  u0.y = tanh_fast(y0);
            u3.x = tanh_fast(x3);  u3.y = tanh_fast(y3);
        }
    }

    *(float2*)(out + g0)          = u0;
    *(float2*)(out + g0 + NS)     = u1;
    *(float2*)(out + g0 + 2 * NS) = u2;
    *(float2*)(out + g0 + 3 * NS) = u3;
}

extern "C" void kernel_launch(void* const* d_in, const int* in_sizes, int n_in,
                              void* d_out, int out_size) {
    const float* X      = (const float*)d_in[0];
    const float* pred   = (const float*)d_in[1];
    const float* w      = (const float*)d_in[2];
    const float* a      = (const float*)d_in[3];
    const float* bias   = (const float*)d_in[4];
    const float* scalar = (const float*)d_in[5];
    float* out = (float*)d_out;

    const int B = in_sizes[0] / 4096;   // batch = 128
    prop_kernel<<<B, 512>>>(X, pred, w, a, bias, scalar, out);
}